// round 7
// baseline (speedup 1.0000x reference)
#include <cuda_runtime.h>
#include <cuda_bf16.h>
#include <cstdint>

#define BB 4
#define CDIM 128
#define ICD 64
#define NPIX 4096
#define LOG2E 1.4426950408889634f
#define QT 64            // queries per CTA (2 independent CTAs per former 128-q tile)
#define KT 128
#define NIT (NPIX / KT)
#define PAD 72           // bf16 elements per smem row (144 B) in attn tiles

// ---------------- scratch (device globals; allocation-free) ----------------
// theta is PRE-SCALED by LOG2E (so attn can ex2 the raw MMA output).
__device__ __nv_bfloat16 g_thetaB[BB * NPIX * ICD];  // [b][n][i]
__device__ __nv_bfloat16 g_phiB  [BB * NPIX * ICD];  // [b][n][i]
__device__ __nv_bfloat16 g_gB    [BB * NPIX * ICD];  // [b][n][i]

__device__ __forceinline__ float ex2f(float x) {
    float y; asm("ex2.approx.ftz.f32 %0, %1;" : "=f"(y) : "f"(x)); return y;
}
__device__ __forceinline__ uint32_t smem_u32(const void* p) {
    uint32_t a;
    asm("{ .reg .u64 t; cvta.to.shared.u64 t, %1; cvt.u32.u64 %0, t; }" : "=r"(a) : "l"(p));
    return a;
}
__device__ __forceinline__ void cp16(uint32_t dst, const void* src) {
    asm volatile("cp.async.cg.shared.global [%0], [%1], 16;" :: "r"(dst), "l"(src));
}
#define CP_COMMIT() asm volatile("cp.async.commit_group;" ::: "memory")
#define CP_WAIT0()  asm volatile("cp.async.wait_group 0;" ::: "memory")

__device__ __forceinline__ void ldm4(uint32_t* r, uint32_t a) {
    asm volatile("ldmatrix.sync.aligned.m8n8.x4.shared.b16 {%0,%1,%2,%3}, [%4];"
                 : "=r"(r[0]), "=r"(r[1]), "=r"(r[2]), "=r"(r[3]) : "r"(a));
}
__device__ __forceinline__ void ldm4t(uint32_t* r, uint32_t a) {
    asm volatile("ldmatrix.sync.aligned.m8n8.x4.trans.shared.b16 {%0,%1,%2,%3}, [%4];"
                 : "=r"(r[0]), "=r"(r[1]), "=r"(r[2]), "=r"(r[3]) : "r"(a));
}
__device__ __forceinline__ void mma16816(float* d, const uint32_t* a, const uint32_t* b) {
    asm volatile("mma.sync.aligned.m16n8k16.row.col.f32.bf16.bf16.f32 "
                 "{%0,%1,%2,%3}, {%4,%5,%6,%7}, {%8,%9}, {%0,%1,%2,%3};"
                 : "+f"(d[0]), "+f"(d[1]), "+f"(d[2]), "+f"(d[3])
                 : "r"(a[0]), "r"(a[1]), "r"(a[2]), "r"(a[3]), "r"(b[0]), "r"(b[1]));
}
__device__ __forceinline__ uint32_t packbf(float a, float b) {
    __nv_bfloat162 v = __floats2bfloat162_rn(a, b);
    return *reinterpret_cast<uint32_t*>(&v);
}

// ============================================================================
// Kernel A: fused 1x1-conv projections via HMMA (unchanged from round 6).
// ============================================================================
#define PRJ_XS 0
#define PRJ_WS 34816
#define PRJ_BIAS 87040
#define PRJ_SM 87808
#define PRJROW 272

__global__ __launch_bounds__(256, 1) void proj_kernel(const float* __restrict__ x,
                            const float* __restrict__ gw, const float* __restrict__ gb,
                            const float* __restrict__ tw, const float* __restrict__ tb,
                            const float* __restrict__ pw, const float* __restrict__ pb)
{
    extern __shared__ char smc[];
    const uint32_t smb = smem_u32(smc);
    const int tid  = threadIdx.x;
    const int lane = tid & 31;
    const int warp = tid >> 5;
    const int b  = blockIdx.y;
    const int n0 = blockIdx.x * 128;

    const int g  = lane >> 3;
    const int l8 = lane & 7;

    const float* xb = x + (size_t)b * CDIM * NPIX + n0;
    #pragma unroll
    for (int i = tid; i < 128 * 32; i += 256) {
        int c = i >> 5, f = i & 31;
        float4 v = *(const float4*)(xb + (size_t)c * NPIX + f * 4);
        uint2 u;
        u.x = packbf(v.x, v.y);
        u.y = packbf(v.z, v.w);
        *(uint2*)(smc + PRJ_XS + c * PRJROW + f * 8) = u;
    }
    #pragma unroll
    for (int i = tid; i < 192 * 16; i += 256) {
        int r = i >> 4, u = i & 15;
        const float* src = (r < 64) ? (tw + r * 128)
                         : (r < 128) ? (pw + (r - 64) * 128)
                                     : (gw + (r - 128) * 128);
        float4 f0 = *(const float4*)(src + u * 8);
        float4 f1 = *(const float4*)(src + u * 8 + 4);
        uint4 v;
        v.x = packbf(f0.x, f0.y); v.y = packbf(f0.z, f0.w);
        v.z = packbf(f1.x, f1.y); v.w = packbf(f1.z, f1.w);
        *(uint4*)(smc + PRJ_WS + r * PRJROW + u * 16) = v;
    }
    if (tid < 192) {
        float bv = (tid < 64) ? tb[tid] : (tid < 128) ? pb[tid - 64] : gb[tid - 128];
        ((float*)(smc + PRJ_BIAS))[tid] = bv;
    }
    __syncthreads();

    const int wm = warp * 16;

    uint32_t Ax[8][4];
    #pragma unroll
    for (int kf = 0; kf < 8; kf++)
        ldm4t(Ax[kf], smb + PRJ_XS
                      + (uint32_t)(kf * 16 + (g >> 1) * 8 + l8) * PRJROW
                      + (uint32_t)(wm + (g & 1) * 8) * 2);

    float D[24][4];
    #pragma unroll
    for (int i = 0; i < 24; i++)
        #pragma unroll
        for (int j = 0; j < 4; j++) D[i][j] = 0.f;

    #pragma unroll
    for (int ib = 0; ib < 12; ib++) {
        #pragma unroll
        for (int kf = 0; kf < 8; kf++) {
            uint32_t bf[4];
            ldm4(bf, smb + PRJ_WS
                     + (uint32_t)(ib * 16 + (g >> 1) * 8 + l8) * PRJROW
                     + (uint32_t)(kf * 16 + (g & 1) * 8) * 2);
            mma16816(D[2 * ib],     Ax[kf], bf);
            mma16816(D[2 * ib + 1], Ax[kf], bf + 2);
        }
    }

    const float* sbias = (const float*)(smc + PRJ_BIAS);
    const int r  = lane >> 2;
    const int c2 = (lane & 3) * 2;
    const size_t nlo = (size_t)(b * NPIX + n0 + wm + r) * ICD;
    const size_t nhi = nlo + 8 * ICD;
    #pragma unroll
    for (int db = 0; db < 24; db++) {
        int ig = db * 8 + c2;
        float b0 = sbias[ig], b1 = sbias[ig + 1];
        float v0 = D[db][0] + b0, v1 = D[db][1] + b1;
        float v2 = D[db][2] + b0, v3 = D[db][3] + b1;
        __nv_bfloat16* dst;
        if (ig < 64) {
            dst = g_thetaB;
            v0 *= LOG2E; v1 *= LOG2E; v2 *= LOG2E; v3 *= LOG2E;
        } else if (ig < 128) dst = g_phiB;
        else                 dst = g_gB;
        int io = ig & 63;
        *(uint32_t*)&dst[nlo + io] = packbf(v0, v1);
        *(uint32_t*)&dst[nhi + io] = packbf(v2, v3);
    }
}

// ============================================================================
// Kernel B: HMMA flash attention + fused output GEMM + residual.
// NOW: 128 threads (4 warps), 64 queries/CTA, 2 CTAs/SM for cross-CTA overlap.
// smem: Q/W region @0 (18432 B; Q uses 64 rows, W epilogue uses 128 rows),
//       K0,V0,K1,V1 @18432 (4 x 18432) -> total 92160 per CTA.
// ============================================================================
#define SMQ 0
#define SMKV 18432
#define SM_TOTAL 92160

__global__ __launch_bounds__(128, 2) void attn_kernel(const float* __restrict__ x,
                                                      const float* __restrict__ Ww,
                                                      const float* __restrict__ Wb,
                                                      float* __restrict__ out)
{
    extern __shared__ char smc[];
    const uint32_t smb = smem_u32(smc);
    const int tid  = threadIdx.x;
    const int lane = tid & 31;
    const int warp = tid >> 5;          // 0..3
    const int b  = blockIdx.y;
    const int q0 = blockIdx.x * QT;
    const int q0w = warp * 16;

    const int g  = lane >> 3;
    const int l8 = lane & 7;
    const int rowA = (g & 1) * 8 + l8;   // A-operand (Q / P / y) from [m][k]
    const int colA = (g >> 1) * 8;
    const int rowB = (g >> 1) * 8 + l8;  // B-operand non-trans (K / Ww) from [n][k]
    const int colB = (g & 1) * 8;
    const int rowV = (g & 1) * 8 + l8;   // B-operand trans (V) from [k][n]
    const int colV = (g >> 1) * 8;

    // ---- load Q tile (theta, pre-scaled by LOG2E) [64 x 64] -> smem ----
    {
        const __nv_bfloat16* th = g_thetaB + ((size_t)(b * NPIX) + q0) * ICD;
        #pragma unroll
        for (int i = tid; i < 512; i += 128) {
            int row = i >> 3, u = i & 7;
            *(uint4*)(smc + SMQ + row * 144 + u * 16) = *(const uint4*)(th + row * 64 + u * 8);
        }
    }
    __syncthreads();

    uint32_t Aq[4][4];
    #pragma unroll
    for (int kf = 0; kf < 4; kf++)
        ldm4(Aq[kf], smb + SMQ + (uint32_t)((q0w + rowA) * PAD + kf * 16 + colA) * 2);
    __syncthreads();   // Q smem free (epilogue reuses it)

    const __nv_bfloat16* phB = g_phiB + (size_t)(b * NPIX) * ICD;
    const __nv_bfloat16* gvB = g_gB   + (size_t)(b * NPIX) * ICD;
    auto prefetch = [&](int t) {
        const uint32_t kb = smb + SMKV + (t & 1) * 36864;
        const uint32_t vb = kb + 18432;
        const int k0 = t * KT;
        #pragma unroll
        for (int i = tid; i < 1024; i += 128) {
            int row = i >> 3, u = i & 7;
            cp16(kb + row * 144 + u * 16, phB + (size_t)(k0 + row) * ICD + u * 8);
            cp16(vb + row * 144 + u * 16, gvB + (size_t)(k0 + row) * ICD + u * 8);
        }
        CP_COMMIT();
    };

    prefetch(0);

    float O[8][4];
    #pragma unroll
    for (int i = 0; i < 8; i++)
        #pragma unroll
        for (int j = 0; j < 4; j++) O[i][j] = 0.f;
    float lsum0 = 0.f, lsum1 = 0.f;

    #pragma unroll 1
    for (int t = 0; t < NIT; t++) {
        CP_WAIT0();
        __syncthreads();
        if (t + 1 < NIT) prefetch(t + 1);

        const uint32_t kb = smb + SMKV + (t & 1) * 36864;
        const uint32_t vb = kb + 18432;

        // ---- S = Q . K^T  (16q x 128k per warp); S already in log2 domain ----
        float S[16][4];
        #pragma unroll
        for (int i = 0; i < 16; i++)
            #pragma unroll
            for (int j = 0; j < 4; j++) S[i][j] = 0.f;

        #pragma unroll
        for (int nbp = 0; nbp < 8; nbp++) {
            #pragma unroll
            for (int kf = 0; kf < 4; kf++) {
                uint32_t bf[4];
                ldm4(bf, kb + (uint32_t)((nbp * 16 + rowB) * PAD + kf * 16 + colB) * 2);
                mma16816(S[2 * nbp],     Aq[kf], bf);
                mma16816(S[2 * nbp + 1], Aq[kf], bf + 2);
            }
        }

        // ---- fused per-16-key chunk: exp + pack + PV MMAs ----
        #pragma unroll
        for (int kf2 = 0; kf2 < 8; kf2++) {
            float e0 = ex2f(S[2 * kf2][0]);
            float e1 = ex2f(S[2 * kf2][1]);
            float e2 = ex2f(S[2 * kf2][2]);
            float e3 = ex2f(S[2 * kf2][3]);
            float e4 = ex2f(S[2 * kf2 + 1][0]);
            float e5 = ex2f(S[2 * kf2 + 1][1]);
            float e6 = ex2f(S[2 * kf2 + 1][2]);
            float e7 = ex2f(S[2 * kf2 + 1][3]);
            lsum0 += (e0 + e1) + (e4 + e5);
            lsum1 += (e2 + e3) + (e6 + e7);
            uint32_t a[4];
            a[0] = packbf(e0, e1);
            a[1] = packbf(e2, e3);
            a[2] = packbf(e4, e5);
            a[3] = packbf(e6, e7);
            #pragma unroll
            for (int dbp = 0; dbp < 4; dbp++) {
                uint32_t bf[4];
                ldm4t(bf, vb + (uint32_t)((kf2 * 16 + rowV) * PAD + dbp * 16 + colV) * 2);
                mma16816(O[2 * dbp],     a, bf);
                mma16816(O[2 * dbp + 1], a, bf + 2);
            }
        }
    }

    // ---- row-sum reduction across the 4 lanes sharing a row ----
    lsum0 += __shfl_xor_sync(0xffffffffu, lsum0, 1);
    lsum0 += __shfl_xor_sync(0xffffffffu, lsum0, 2);
    lsum1 += __shfl_xor_sync(0xffffffffu, lsum1, 1);
    lsum1 += __shfl_xor_sync(0xffffffffu, lsum1, 2);
    const float rin0 = 1.f / lsum0;
    const float rin1 = 1.f / lsum1;

    __syncthreads();  // everyone done with KV smem

    // ---- load W_w [128c x 64i] fp32 -> bf16 smem (reuse Q region, 128 rows) ----
    #pragma unroll
    for (int i = tid; i < 1024; i += 128) {
        int row = i >> 3, u = i & 7;
        const float* s = Ww + row * 64 + u * 8;
        float4 f0 = *(const float4*)s;
        float4 f1 = *(const float4*)(s + 4);
        uint4 v;
        v.x = packbf(f0.x, f0.y); v.y = packbf(f0.z, f0.w);
        v.z = packbf(f1.x, f1.y); v.w = packbf(f1.z, f1.w);
        *(uint4*)(smc + SMQ + row * 144 + u * 16) = v;
    }
    __syncthreads();

    // ---- MMA3: D[16q x 128c] = y_bf16 . Ww^T ----
    uint32_t Ay[4][4];
    #pragma unroll
    for (int kf = 0; kf < 4; kf++) {
        Ay[kf][0] = packbf(O[2 * kf][0] * rin0,     O[2 * kf][1] * rin0);
        Ay[kf][1] = packbf(O[2 * kf][2] * rin1,     O[2 * kf][3] * rin1);
        Ay[kf][2] = packbf(O[2 * kf + 1][0] * rin0, O[2 * kf + 1][1] * rin0);
        Ay[kf][3] = packbf(O[2 * kf + 1][2] * rin1, O[2 * kf + 1][3] * rin1);
    }

    float D[16][4];
    #pragma unroll
    for (int i = 0; i < 16; i++)
        #pragma unroll
        for (int j = 0; j < 4; j++) D[i][j] = 0.f;

    #pragma unroll
    for (int nbp = 0; nbp < 8; nbp++) {
        #pragma unroll
        for (int kf = 0; kf < 4; kf++) {
            uint32_t bf[4];
            ldm4(bf, smb + SMQ + (uint32_t)((nbp * 16 + rowB) * PAD + kf * 16 + colB) * 2);
            mma16816(D[2 * nbp],     Ay[kf], bf);
            mma16816(D[2 * nbp + 1], Ay[kf], bf + 2);
        }
    }

    // ---- transpose D via smem: smt[c][68] fp32 (overlays KV buffers) ----
    float* smt = (float*)(smc + SMKV);
    {
        const int qr = q0w + (lane >> 2);
        const int cb = 2 * (lane & 3);
        #pragma unroll
        for (int nb = 0; nb < 16; nb++) {
            int c = nb * 8 + cb;
            smt[(c    ) * 68 + qr    ] = D[nb][0];
            smt[(c + 1) * 68 + qr    ] = D[nb][1];
            smt[(c    ) * 68 + qr + 8] = D[nb][2];
            smt[(c + 1) * 68 + qr + 8] = D[nb][3];
        }
    }
    __syncthreads();

    // ---- out[b][c][q0+q] = D^T + Wb[c] + x ----
    #pragma unroll
    for (int idx = tid; idx < CDIM * 16; idx += 128) {
        int c = idx >> 4, qf = idx & 15;
        float4 v = *(const float4*)&smt[c * 68 + qf * 4];
        float bv = Wb[c];
        size_t gi = ((size_t)(b * CDIM + c)) * NPIX + q0 + qf * 4;
        float4 xv = *(const float4*)&x[gi];
        v.x += bv + xv.x; v.y += bv + xv.y; v.z += bv + xv.z; v.w += bv + xv.w;
        *(float4*)&out[gi] = v;
    }
}

// ============================================================================
extern "C" void kernel_launch(void* const* d_in, const int* in_sizes, int n_in,
                              void* d_out, int out_size)
{
    const float* x       = (const float*)d_in[0];
    const float* g_w     = (const float*)d_in[1];
    const float* g_b     = (const float*)d_in[2];
    const float* theta_w = (const float*)d_in[3];
    const float* theta_b = (const float*)d_in[4];
    const float* phi_w   = (const float*)d_in[5];
    const float* phi_b   = (const float*)d_in[6];
    const float* W_w     = (const float*)d_in[7];
    const float* W_b     = (const float*)d_in[8];
    float* out = (float*)d_out;

    cudaFuncSetAttribute(proj_kernel, cudaFuncAttributeMaxDynamicSharedMemorySize, PRJ_SM);
    cudaFuncSetAttribute(attn_kernel, cudaFuncAttributeMaxDynamicSharedMemorySize, SM_TOTAL);

    proj_kernel<<<dim3(NPIX / 128, BB), 256, PRJ_SM>>>(x, g_w, g_b, theta_w, theta_b, phi_w, phi_b);
    attn_kernel<<<dim3(NPIX / QT, BB), 128, SM_TOTAL>>>(x, W_w, W_b, out);
}